// round 15
// baseline (speedup 1.0000x reference)
#include <cuda_runtime.h>
#include <cuda_fp16.h>
#include <math.h>
#include <cstdint>

// Problem constants
#define Bb  2
#define Ll  12
#define Nn  2048
#define Hh  64
#define NDe 32
#define TEe 10
#define Ff  148
#define F2  116
#define KTt 3

static const size_t OUT_G = (size_t)Bb * Nn * KTt * Nn;

// Scratch (allocation-free rule: device globals)
__device__ float g_feat[(size_t)Bb * Nn * Ff];
__device__ __half g_Qh[(size_t)4 * Nn * Hh];   // 0.125*Q hi (fp16)
__device__ __half g_Ql[(size_t)4 * Nn * Hh];   // 0.125*Q lo
__device__ __half g_Kh[(size_t)4 * Nn * Hh];   // K hi
__device__ __half g_Kl[(size_t)4 * Nn * Hh];   // K lo
__device__ float g_S[(size_t)4 * Nn * Nn];
__device__ __half g_Ah[(size_t)4 * Nn * Nn];   // A (fp16), row-major [m][k]

// ===========================================================================
// Baseline-ISA helpers
// ===========================================================================
__device__ __forceinline__ void cpa16(uint32_t dst, const void* src) {
    asm volatile("cp.async.cg.shared.global [%0], [%1], 16;"
                 :: "r"(dst), "l"(src));
}
__device__ __forceinline__ void cpa_commit() {
    asm volatile("cp.async.commit_group;" ::: "memory");
}
template <int N> __device__ __forceinline__ void cpa_wait() {
    asm volatile("cp.async.wait_group %0;" :: "n"(N) : "memory");
}
__device__ __forceinline__ uint32_t s2u(const void* p) {
    uint32_t a;
    asm("{ .reg .u64 t; cvta.to.shared.u64 t, %1; cvt.u32.u64 %0, t; }"
        : "=r"(a) : "l"(p));
    return a;
}
__device__ __forceinline__ void mma16816h(float* d, const uint32_t* a,
                                          const uint32_t* b) {
    asm volatile(
        "mma.sync.aligned.m16n8k16.row.col.f32.f16.f16.f32 "
        "{%0,%1,%2,%3}, {%4,%5,%6,%7}, {%8,%9}, {%0,%1,%2,%3};"
        : "+f"(d[0]), "+f"(d[1]), "+f"(d[2]), "+f"(d[3])
        : "r"(a[0]), "r"(a[1]), "r"(a[2]), "r"(a[3]), "r"(b[0]), "r"(b[1]));
}
__device__ __forceinline__ void ldm4(uint32_t* r, uint32_t addr) {
    asm volatile("ldmatrix.sync.aligned.m8n8.x4.shared.b16 {%0,%1,%2,%3}, [%4];"
                 : "=r"(r[0]), "=r"(r[1]), "=r"(r[2]), "=r"(r[3]) : "r"(addr));
}
__device__ __forceinline__ void ldm4t(uint32_t* r, uint32_t addr) {
    asm volatile("ldmatrix.sync.aligned.m8n8.x4.trans.shared.b16 {%0,%1,%2,%3}, [%4];"
                 : "=r"(r[0]), "=r"(r[1]), "=r"(r[2]), "=r"(r[3]) : "r"(addr));
}

// ---------------------------------------------------------------------------
// Kernel 1: per-node feature prep. 8 nodes per CTA (weight staging amortized).
// ---------------------------------------------------------------------------
__global__ void __launch_bounds__(128) feat_kernel(
    const float* __restrict__ hist, const float* __restrict__ embd,
    const float* __restrict__ embu, const float* __restrict__ tdf,
    const float* __restrict__ dwf,
    const float* __restrict__ W1, const float* __restrict__ b1,
    const float* __restrict__ gamma, const float* __restrict__ beta,
    const float* __restrict__ mean, const float* __restrict__ var,
    const float* __restrict__ W2, const float* __restrict__ b2)
{
    int n0 = blockIdx.x * 8, b = blockIdx.y, t = threadIdx.x;
    __shared__ float Xs[8][12];
    __shared__ float hs[8][128];
    __shared__ float fs[8][64];
    __shared__ float W1s[128 * 12];
    __shared__ float W2s[128 * 65];

    for (int i = t; i < 128 * 12; i += 128) W1s[i] = W1[i];
    for (int i = t; i < 64 * 128; i += 128) {
        int j = i >> 7, k = i & 127;
        W2s[k * 65 + j] = W2[i];
    }
    if (t < 96) {
        int nn = t / 12, l = t - nn * 12;
        Xs[nn][l] = hist[(((size_t)b * Ll + l) * Nn + n0 + nn) * 3];
    }
    __syncthreads();

    {
        float bnb = beta[t], bnm = mean[t];
        float bns = gamma[t] / sqrtf(var[t] + 1e-5f);
        float bias = b1[t];
        #pragma unroll
        for (int nn = 0; nn < 8; nn++) {
            float acc = bias;
            #pragma unroll
            for (int l = 0; l < 12; l++)
                acc = fmaf(Xs[nn][l], W1s[t * 12 + l], acc);
            acc = fmaxf(acc, 0.0f);
            hs[nn][t] = (acc - bnm) * bns + bnb;
        }
    }
    __syncthreads();

    {
        int j = t & 63;
        float bias = b2[j];
        for (int nn = t >> 6; nn < 8; nn += 2) {
            float acc = bias;
            #pragma unroll 16
            for (int k = 0; k < 128; k++)
                acc = fmaf(hs[nn][k], W2s[k * 65 + j], acc);
            fs[nn][j] = acc;
        }
    }
    __syncthreads();

    for (int idx = t; idx < 8 * Ff; idx += 128) {
        int nn = idx / Ff, f = idx - nn * Ff;
        int n = n0 + nn;
        size_t tbase = (((size_t)b * Ll + (Ll - 1)) * Nn + n) * TEe;
        float val;
        if      (f < 64)  val = fs[nn][f];
        else if (f < 74)  val = tdf[tbase + f - 64];
        else if (f < 84)  val = dwf[tbase + f - 74];
        else if (f < 116) val = embd[(size_t)n * NDe + (f - 84)];
        else              val = embu[(size_t)n * NDe + (f - 116)];
        g_feat[((size_t)b * Nn + n) * Ff + f] = val;
    }
}

// ---------------------------------------------------------------------------
// Kernel 2: Q/K projections -> fp16 hi/lo (Q pre-scaled by 1/sqrt(H))
// ---------------------------------------------------------------------------
#define QK_SMEM ((Ff * 128 + 2 * F2 * 64) * (int)sizeof(float))

__global__ void __launch_bounds__(256) qk_kernel(
    const float* __restrict__ WQ, const float* __restrict__ WK)
{
    extern __shared__ float sm[];
    float* Fs  = sm;
    float* WQt = Fs + Ff * 128;
    float* WKt = WQt + F2 * 64;

    int node0 = blockIdx.x * 128;
    int b = blockIdx.y;
    int t = threadIdx.x;

    for (int i = t; i < 128 * Ff; i += 256) {
        int node = i / Ff, f = i - node * Ff;
        Fs[f * 128 + node] = g_feat[((size_t)b * Nn + node0 + node) * Ff + f];
    }
    for (int i = t; i < 64 * F2; i += 256) {
        int j = i / F2, f = i - j * F2;
        WQt[f * 64 + j] = WQ[i];
        WKt[f * 64 + j] = WK[i];
    }
    __syncthreads();

    int v = t >> 7, sel = (t >> 6) & 1, j = t & 63;
    const float* Wt = sel ? WKt : WQt;
    __half* dh = (sel ? g_Kh : g_Qh) + (size_t)(v * 2 + b) * Nn * Hh;
    __half* dl = (sel ? g_Kl : g_Ql) + (size_t)(v * 2 + b) * Nn * Hh;
    float scale = sel ? 1.0f : 0.125f;
    int ebase = 84 + 32 * v;

    for (int nb = 0; nb < 128; nb += 8) {
        float acc[8] = {0, 0, 0, 0, 0, 0, 0, 0};
        for (int f = 0; f < 84; f++) {
            float w = Wt[f * 64 + j];
            #pragma unroll
            for (int u = 0; u < 8; u++)
                acc[u] = fmaf(Fs[f * 128 + nb + u], w, acc[u]);
        }
        #pragma unroll 8
        for (int e = 0; e < 32; e++) {
            float w = Wt[(84 + e) * 64 + j];
            #pragma unroll
            for (int u = 0; u < 8; u++)
                acc[u] = fmaf(Fs[(ebase + e) * 128 + nb + u], w, acc[u]);
        }
        #pragma unroll
        for (int u = 0; u < 8; u++) {
            float sv = acc[u] * scale;
            __half h = __float2half_rn(sv);
            float lo = sv - __half2float(h);
            size_t idx = (size_t)(node0 + nb + u) * Hh + j;
            dh[idx] = h;
            dl[idx] = __float2half_rn(lo);
        }
    }
}

// ---------------------------------------------------------------------------
// Kernel 3: scores for ALL 4 combos in one packed launch (grid z = combo).
// fp16 HMMA, 3-pass hi/lo (exact).
// ---------------------------------------------------------------------------
#define SCSTRIDE 72
#define SC_ARR (128 * SCSTRIDE * 2)
#define SC_SMEM (4 * SC_ARR)

__global__ void __launch_bounds__(256, 2) scores_mma_kernel()
{
    extern __shared__ char dsm[];
    int c = blockIdx.z;
    int row0 = blockIdx.y * 128, col0 = blockIdx.x * 128;
    int t = threadIdx.x, wid = t >> 5, lane = t & 31;
    int g = lane >> 2, tig = lane & 3;
    int wm = wid >> 2, wn = wid & 3;
    int lq = lane >> 3, lr = lane & 7;

    size_t qb = (size_t)c * Nn * Hh;
    uint32_t sb = s2u(dsm);
    uint32_t aQh = sb, aQl = sb + SC_ARR, aKh = sb + 2 * SC_ARR,
             aKl = sb + 3 * SC_ARR;

    #pragma unroll
    for (int j = 0; j < 16; j++) {
        int idx = j * 256 + t;
        int arr = idx >> 10;
        int rem = idx & 1023;
        int rr = rem >> 3, seg = rem & 7;
        const __half* base = (arr == 0) ? g_Qh : (arr == 1) ? g_Ql
                           : (arr == 2) ? g_Kh : g_Kl;
        int grow = ((arr < 2) ? row0 : col0) + rr;
        cpa16(sb + (uint32_t)arr * SC_ARR + rr * (SCSTRIDE * 2) + seg * 16,
              base + qb + (size_t)grow * Hh + seg * 8);
    }
    cpa_commit();
    cpa_wait<0>();
    __syncthreads();

    float acc[4][4][4] = {};
    #pragma unroll
    for (int ks = 0; ks < 4; ks++) {
        int kk = ks * 16;
        uint32_t qh[4][4], ql[4][4], kh[4][2], kl[4][2];
        #pragma unroll
        for (int ma = 0; ma < 4; ma++) {
            int row = wm * 64 + ma * 16 + (lq & 1) * 8 + lr;
            int col = kk + (lq >> 1) * 8;
            uint32_t off = (uint32_t)(row * SCSTRIDE + col) * 2;
            ldm4(qh[ma], aQh + off);
            ldm4(ql[ma], aQl + off);
        }
        #pragma unroll
        for (int np = 0; np < 2; np++) {
            int nrow = wn * 32 + np * 16 + (lq >> 1) * 8 + lr;
            int col = kk + (lq & 1) * 8;
            uint32_t off = (uint32_t)(nrow * SCSTRIDE + col) * 2;
            uint32_t r4[4];
            ldm4(r4, aKh + off);
            kh[np * 2][0] = r4[0]; kh[np * 2][1] = r4[1];
            kh[np * 2 + 1][0] = r4[2]; kh[np * 2 + 1][1] = r4[3];
            ldm4(r4, aKl + off);
            kl[np * 2][0] = r4[0]; kl[np * 2][1] = r4[1];
            kl[np * 2 + 1][0] = r4[2]; kl[np * 2 + 1][1] = r4[3];
        }
        #pragma unroll
        for (int ma = 0; ma < 4; ma++)
            #pragma unroll
            for (int na = 0; na < 4; na++) {
                mma16816h(acc[ma][na], qh[ma], kh[na]);
                mma16816h(acc[ma][na], qh[ma], kl[na]);
                mma16816h(acc[ma][na], ql[ma], kh[na]);
            }
    }

    float* S = g_S + (size_t)c * Nn * Nn;
    #pragma unroll
    for (int ma = 0; ma < 4; ma++)
        #pragma unroll
        for (int rr = 0; rr < 2; rr++) {
            int n = row0 + wm * 64 + ma * 16 + g + rr * 8;
            #pragma unroll
            for (int na = 0; na < 4; na++) {
                int col = col0 + wn * 32 + na * 8 + tig * 2;
                *(float2*)(S + (size_t)n * Nn + col) =
                    make_float2(acc[ma][na][rr * 2 + 0], acc[ma][na][rr * 2 + 1]);
            }
        }
}

// ---------------------------------------------------------------------------
// Kernel 4: softmax -> A (fp16) ONLY. The 192 MB order-1 output write is
// split out into out1_kernel (no downstream dependency -> hidden under sq).
// All 4 combos packed (grid = (Nn, 4)).
// ---------------------------------------------------------------------------
__global__ void __launch_bounds__(256) softmax_kernel(
    const float* __restrict__ mask0, const float* __restrict__ mask1)
{
    int n = blockIdx.x, c = blockIdx.y, v = c >> 1;
    int t = threadIdx.x;
    const float* srow = g_S + ((size_t)c * Nn + n) * Nn;
    const float* mrow = (v ? mask1 : mask0) + (size_t)n * Nn;

    float s[8];
    float lmax = -3.4e38f;
    #pragma unroll
    for (int i = 0; i < 8; i++) {
        s[i] = srow[t + i * 256];
        lmax = fmaxf(lmax, s[i]);
    }

    __shared__ float red[8];
    #pragma unroll
    for (int o = 16; o; o >>= 1)
        lmax = fmaxf(lmax, __shfl_xor_sync(0xffffffffu, lmax, o));
    if ((t & 31) == 0) red[t >> 5] = lmax;
    __syncthreads();
    float rmax = red[0];
    #pragma unroll
    for (int w = 1; w < 8; w++) rmax = fmaxf(rmax, red[w]);
    __syncthreads();

    float wv[8], lsum = 0.0f;
    #pragma unroll
    for (int i = 0; i < 8; i++) {
        wv[i] = (mrow[t + i * 256] + 1e-7f) * expf(s[i] - rmax);
        lsum += wv[i];
    }
    #pragma unroll
    for (int o = 16; o; o >>= 1)
        lsum += __shfl_xor_sync(0xffffffffu, lsum, o);
    if ((t & 31) == 0) red[t >> 5] = lsum;
    __syncthreads();
    float tot = 0.0f;
    #pragma unroll
    for (int w = 0; w < 8; w++) tot += red[w];
    float inv = 1.0f / tot;

    size_t abase = ((size_t)c * Nn + n) * Nn;
    #pragma unroll
    for (int i = 0; i < 8; i++) {
        int m = t + i * 256;
        g_Ah[abase + m] = __float2half_rn(wv[i] * inv);
    }
}

// ---------------------------------------------------------------------------
// Kernel 4b: persistent order-1 output writer. Reads A (fp16), writes the
// diag-zeroed, KT=3-replicated order-1 tensors. Grid = 148 (one CTA per SM,
// 0 smem) so its CTAs co-reside with sq and stream on otherwise-idle DRAM.
// ---------------------------------------------------------------------------
__global__ void __launch_bounds__(256) out1_kernel(float* __restrict__ out)
{
    int t = threadIdx.x;
    for (int rid = blockIdx.x; rid < 4 * Nn; rid += gridDim.x) {
        int c = rid >> 11, n = rid & (Nn - 1);
        int v = c >> 1, b = c & 1;
        const __half* arow = g_Ah + ((size_t)c * Nn + n) * Nn;
        float* orow = out + (size_t)(v * 2) * OUT_G
                          + (size_t)(b * Nn + n) * (KTt * Nn);
        int col = t * 8;
        uint4 raw = *(const uint4*)(arow + col);
        __half2 h0 = *(__half2*)&raw.x, h1 = *(__half2*)&raw.y;
        __half2 h2 = *(__half2*)&raw.z, h3 = *(__half2*)&raw.w;
        float2 f0 = __half22float2(h0), f1 = __half22float2(h1);
        float2 f2 = __half22float2(h2), f3 = __half22float2(h3);
        float vals[8] = { f0.x, f0.y, f1.x, f1.y, f2.x, f2.y, f3.x, f3.y };
        int dd = n - col;
        if (dd >= 0 && dd < 8) vals[dd] = 0.0f;
        float4 o0 = *(float4*)&vals[0];
        float4 o1 = *(float4*)&vals[4];
        #pragma unroll
        for (int r = 0; r < KTt; r++) {
            *(float4*)(orow + (size_t)r * Nn + col)     = o0;
            *(float4*)(orow + (size_t)r * Nn + col + 4) = o1;
        }
    }
}

// ---------------------------------------------------------------------------
// Kernel 5: C = A @ A via fp16 mma.sync, ALL 4 combos packed (grid z = combo).
// Single pass, B via ldmatrix.trans. CTA 128x128, 4 warps of 64x64,
// K-chunk 64, double-buffered cp.async. Epilogue: diag zero, x3 replicate.
// ---------------------------------------------------------------------------
#define ASTRIDE 72
#define BSTRIDE 136
#define A_B (128 * ASTRIDE * 2)
#define B_B (64 * BSTRIDE * 2)
#define BUF_B (A_B + B_B)
#define SQ_SMEM (2 * BUF_B)

__global__ void __launch_bounds__(128, 2) sq_mma_kernel(float* __restrict__ out)
{
    extern __shared__ char dsm[];
    int c = blockIdx.z, v = c >> 1, b = c & 1;
    int row0 = blockIdx.y * 128, col0 = blockIdx.x * 128;
    int t = threadIdx.x, wid = t >> 5, lane = t & 31;
    int g = lane >> 2, tig = lane & 3;
    int wm = wid >> 1, wn = wid & 1;
    int lq = lane >> 3, lr = lane & 7;

    size_t cb = (size_t)c * Nn * Nn;
    const __half* Ahg = g_Ah + cb;

    uint32_t sbase = s2u(dsm);
    float acc[4][8][4] = {};

    auto load_stage = [&](int s, int kc) {
        uint32_t sb = sbase + (uint32_t)s * BUF_B;
        int k0 = kc * 64;
        #pragma unroll
        for (int j = 0; j < 8; j++) {
            int idx = j * 128 + t;
            int rr = idx >> 3, seg = idx & 7;
            cpa16(sb + rr * (ASTRIDE * 2) + seg * 16,
                  Ahg + (size_t)(row0 + rr) * Nn + k0 + seg * 8);
        }
        #pragma unroll
        for (int j = 0; j < 8; j++) {
            int idx = j * 128 + t;
            int rr = idx >> 4, seg = idx & 15;
            cpa16(sb + A_B + rr * (BSTRIDE * 2) + seg * 16,
                  Ahg + (size_t)(k0 + rr) * Nn + col0 + seg * 8);
        }
        cpa_commit();
    };

    load_stage(0, 0);

    int buf = 0;
    for (int kc = 0; kc < 32; kc++) {
        if (kc + 1 < 32) {
            load_stage(buf ^ 1, kc + 1);
            cpa_wait<1>();
        } else {
            cpa_wait<0>();
        }
        __syncthreads();

        uint32_t sb = sbase + (uint32_t)buf * BUF_B;
        uint32_t aA = sb, aB = sb + A_B;

        #pragma unroll
        for (int ks = 0; ks < 4; ks++) {
            int kk = ks * 16;
            uint32_t ah[4][4], bh[8][2];
            #pragma unroll
            for (int ma = 0; ma < 4; ma++) {
                int row = wm * 64 + ma * 16 + (lq & 1) * 8 + lr;
                int col = kk + (lq >> 1) * 8;
                ldm4(ah[ma], aA + (uint32_t)(row * ASTRIDE + col) * 2);
            }
            #pragma unroll
            for (int np = 0; np < 4; np++) {
                int row_k = kk + (lq & 1) * 8 + lr;
                int col_n = wn * 64 + np * 16 + (lq >> 1) * 8;
                uint32_t r4[4];
                ldm4t(r4, aB + (uint32_t)(row_k * BSTRIDE + col_n) * 2);
                bh[np * 2][0] = r4[0]; bh[np * 2][1] = r4[1];
                bh[np * 2 + 1][0] = r4[2]; bh[np * 2 + 1][1] = r4[3];
            }
            #pragma unroll
            for (int ma = 0; ma < 4; ma++)
                #pragma unroll
                for (int na = 0; na < 8; na++)
                    mma16816h(acc[ma][na], ah[ma], bh[na]);
        }
        __syncthreads();
        buf ^= 1;
    }

    float* obase = out + (size_t)(v * 2 + 1) * OUT_G;
    #pragma unroll
    for (int ma = 0; ma < 4; ma++) {
        #pragma unroll
        for (int rr = 0; rr < 2; rr++) {
            int n = row0 + wm * 64 + ma * 16 + g + rr * 8;
            size_t orow = (size_t)(b * Nn + n) * (KTt * Nn);
            #pragma unroll
            for (int na = 0; na < 8; na++) {
                int col = col0 + wn * 64 + na * 8 + tig * 2;
                float v0 = acc[ma][na][rr * 2 + 0];
                float v1 = acc[ma][na][rr * 2 + 1];
                if (n == col)     v0 = 0.0f;
                if (n == col + 1) v1 = 0.0f;
                float2 o = make_float2(v0, v1);
                *(float2*)(obase + orow + col)          = o;
                *(float2*)(obase + orow + Nn + col)     = o;
                *(float2*)(obase + orow + 2 * Nn + col) = o;
            }
        }
    }
}

// ---------------------------------------------------------------------------
extern "C" void kernel_launch(void* const* d_in, const int* in_sizes, int n_in,
                              void* d_out, int out_size)
{
    const float* hist = (const float*)d_in[0];
    const float* embd = (const float*)d_in[1];
    const float* embu = (const float*)d_in[2];
    const float* tdf  = (const float*)d_in[3];
    const float* dwf  = (const float*)d_in[4];
    const float* m0   = (const float*)d_in[5];
    const float* m1   = (const float*)d_in[6];
    const float* W1   = (const float*)d_in[7];
    const float* b1   = (const float*)d_in[8];
    const float* gam  = (const float*)d_in[9];
    const float* bet  = (const float*)d_in[10];
    const float* mu   = (const float*)d_in[11];
    const float* var  = (const float*)d_in[12];
    const float* W2   = (const float*)d_in[13];
    const float* b2   = (const float*)d_in[14];
    const float* WQ   = (const float*)d_in[15];
    const float* WK   = (const float*)d_in[16];
    float* out = (float*)d_out;

    // One-time host-side resources (un-captured correctness call).
    static cudaStream_t s1 = nullptr;
    static cudaEvent_t evA = nullptr, evB = nullptr;
    if (s1 == nullptr) {
        cudaStreamCreateWithFlags(&s1, cudaStreamNonBlocking);
        cudaEventCreateWithFlags(&evA, cudaEventDisableTiming);
        cudaEventCreateWithFlags(&evB, cudaEventDisableTiming);
        cudaFuncSetAttribute(qk_kernel,
                             cudaFuncAttributeMaxDynamicSharedMemorySize, QK_SMEM);
        cudaFuncSetAttribute(scores_mma_kernel,
                             cudaFuncAttributeMaxDynamicSharedMemorySize, SC_SMEM);
        cudaFuncSetAttribute(sq_mma_kernel,
                             cudaFuncAttributeMaxDynamicSharedMemorySize, SQ_SMEM);
    }

    // Critical path (origin stream): prep -> scores -> A -> sq.
    feat_kernel<<<dim3(Nn / 8, Bb), 128>>>(hist, embd, embu, tdf, dwf,
                                           W1, b1, gam, bet, mu, var, W2, b2);
    qk_kernel<<<dim3(Nn / 128, Bb), 256, QK_SMEM>>>(WQ, WK);
    scores_mma_kernel<<<dim3(16, 16, 4), 256, SC_SMEM>>>();
    softmax_kernel<<<dim3(Nn, 4), 256>>>(m0, m1);
    cudaEventRecord(evA, 0);

    // Side stream: persistent order-1 writer (depends only on A). 148 CTAs,
    // 0 smem -> co-resident with sq, streams on DRAM idle under tensor work.
    cudaStreamWaitEvent(s1, evA, 0);
    out1_kernel<<<148, 256, 0, s1>>>(out);

    // Tensor-bound A@A on the origin stream.
    sq_mma_kernel<<<dim3(16, 16, 4), 128, SQ_SMEM>>>(out);

    // Join.
    cudaEventRecord(evB, s1);
    cudaStreamWaitEvent(0, evB, 0);
}

// round 16
// speedup vs baseline: 1.0985x; 1.0985x over previous
#include <cuda_runtime.h>
#include <cuda_fp16.h>
#include <math.h>
#include <cstdint>

// Problem constants
#define Bb  2
#define Ll  12
#define Nn  2048
#define Hh  64
#define NDe 32
#define TEe 10
#define Ff  148
#define F2  116
#define KTt 3

static const size_t OUT_G = (size_t)Bb * Nn * KTt * Nn;

// Scratch (allocation-free rule: device globals)
__device__ float g_feat[(size_t)Bb * Nn * Ff];
__device__ __half g_Qh[(size_t)4 * Nn * Hh];   // 0.125*Q hi (fp16)
__device__ __half g_Ql[(size_t)4 * Nn * Hh];   // 0.125*Q lo
__device__ __half g_Kh[(size_t)4 * Nn * Hh];   // K hi
__device__ __half g_Kl[(size_t)4 * Nn * Hh];   // K lo
__device__ float g_S[(size_t)4 * Nn * Nn];
__device__ __half g_Ah[(size_t)4 * Nn * Nn];   // A (fp16), row-major [m][k]

// ===========================================================================
// Baseline-ISA helpers
// ===========================================================================
__device__ __forceinline__ void cpa16(uint32_t dst, const void* src) {
    asm volatile("cp.async.cg.shared.global [%0], [%1], 16;"
                 :: "r"(dst), "l"(src));
}
__device__ __forceinline__ void cpa_commit() {
    asm volatile("cp.async.commit_group;" ::: "memory");
}
template <int N> __device__ __forceinline__ void cpa_wait() {
    asm volatile("cp.async.wait_group %0;" :: "n"(N) : "memory");
}
__device__ __forceinline__ uint32_t s2u(const void* p) {
    uint32_t a;
    asm("{ .reg .u64 t; cvta.to.shared.u64 t, %1; cvt.u32.u64 %0, t; }"
        : "=r"(a) : "l"(p));
    return a;
}
__device__ __forceinline__ void mma16816h(float* d, const uint32_t* a,
                                          const uint32_t* b) {
    asm volatile(
        "mma.sync.aligned.m16n8k16.row.col.f32.f16.f16.f32 "
        "{%0,%1,%2,%3}, {%4,%5,%6,%7}, {%8,%9}, {%0,%1,%2,%3};"
        : "+f"(d[0]), "+f"(d[1]), "+f"(d[2]), "+f"(d[3])
        : "r"(a[0]), "r"(a[1]), "r"(a[2]), "r"(a[3]), "r"(b[0]), "r"(b[1]));
}
__device__ __forceinline__ void ldm4(uint32_t* r, uint32_t addr) {
    asm volatile("ldmatrix.sync.aligned.m8n8.x4.shared.b16 {%0,%1,%2,%3}, [%4];"
                 : "=r"(r[0]), "=r"(r[1]), "=r"(r[2]), "=r"(r[3]) : "r"(addr));
}
__device__ __forceinline__ void ldm4t(uint32_t* r, uint32_t addr) {
    asm volatile("ldmatrix.sync.aligned.m8n8.x4.trans.shared.b16 {%0,%1,%2,%3}, [%4];"
                 : "=r"(r[0]), "=r"(r[1]), "=r"(r[2]), "=r"(r[3]) : "r"(addr));
}

// ---------------------------------------------------------------------------
// Kernel 1: per-node feature prep. 8 nodes per CTA (weight staging amortized).
// ---------------------------------------------------------------------------
__global__ void __launch_bounds__(128) feat_kernel(
    const float* __restrict__ hist, const float* __restrict__ embd,
    const float* __restrict__ embu, const float* __restrict__ tdf,
    const float* __restrict__ dwf,
    const float* __restrict__ W1, const float* __restrict__ b1,
    const float* __restrict__ gamma, const float* __restrict__ beta,
    const float* __restrict__ mean, const float* __restrict__ var,
    const float* __restrict__ W2, const float* __restrict__ b2)
{
    int n0 = blockIdx.x * 8, b = blockIdx.y, t = threadIdx.x;
    __shared__ float Xs[8][12];
    __shared__ float hs[8][128];
    __shared__ float fs[8][64];
    __shared__ float W1s[128 * 12];
    __shared__ float W2s[128 * 65];

    for (int i = t; i < 128 * 12; i += 128) W1s[i] = W1[i];
    for (int i = t; i < 64 * 128; i += 128) {
        int j = i >> 7, k = i & 127;
        W2s[k * 65 + j] = W2[i];
    }
    if (t < 96) {
        int nn = t / 12, l = t - nn * 12;
        Xs[nn][l] = hist[(((size_t)b * Ll + l) * Nn + n0 + nn) * 3];
    }
    __syncthreads();

    {
        float bnb = beta[t], bnm = mean[t];
        float bns = gamma[t] / sqrtf(var[t] + 1e-5f);
        float bias = b1[t];
        #pragma unroll
        for (int nn = 0; nn < 8; nn++) {
            float acc = bias;
            #pragma unroll
            for (int l = 0; l < 12; l++)
                acc = fmaf(Xs[nn][l], W1s[t * 12 + l], acc);
            acc = fmaxf(acc, 0.0f);
            hs[nn][t] = (acc - bnm) * bns + bnb;
        }
    }
    __syncthreads();

    {
        int j = t & 63;
        float bias = b2[j];
        for (int nn = t >> 6; nn < 8; nn += 2) {
            float acc = bias;
            #pragma unroll 16
            for (int k = 0; k < 128; k++)
                acc = fmaf(hs[nn][k], W2s[k * 65 + j], acc);
            fs[nn][j] = acc;
        }
    }
    __syncthreads();

    for (int idx = t; idx < 8 * Ff; idx += 128) {
        int nn = idx / Ff, f = idx - nn * Ff;
        int n = n0 + nn;
        size_t tbase = (((size_t)b * Ll + (Ll - 1)) * Nn + n) * TEe;
        float val;
        if      (f < 64)  val = fs[nn][f];
        else if (f < 74)  val = tdf[tbase + f - 64];
        else if (f < 84)  val = dwf[tbase + f - 74];
        else if (f < 116) val = embd[(size_t)n * NDe + (f - 84)];
        else              val = embu[(size_t)n * NDe + (f - 116)];
        g_feat[((size_t)b * Nn + n) * Ff + f] = val;
    }
}

// ---------------------------------------------------------------------------
// Kernel 2: Q/K projections -> fp16 hi/lo (Q pre-scaled by 1/sqrt(H))
// ---------------------------------------------------------------------------
#define QK_SMEM ((Ff * 128 + 2 * F2 * 64) * (int)sizeof(float))

__global__ void __launch_bounds__(256) qk_kernel(
    const float* __restrict__ WQ, const float* __restrict__ WK)
{
    extern __shared__ float sm[];
    float* Fs  = sm;
    float* WQt = Fs + Ff * 128;
    float* WKt = WQt + F2 * 64;

    int node0 = blockIdx.x * 128;
    int b = blockIdx.y;
    int t = threadIdx.x;

    for (int i = t; i < 128 * Ff; i += 256) {
        int node = i / Ff, f = i - node * Ff;
        Fs[f * 128 + node] = g_feat[((size_t)b * Nn + node0 + node) * Ff + f];
    }
    for (int i = t; i < 64 * F2; i += 256) {
        int j = i / F2, f = i - j * F2;
        WQt[f * 64 + j] = WQ[i];
        WKt[f * 64 + j] = WK[i];
    }
    __syncthreads();

    int v = t >> 7, sel = (t >> 6) & 1, j = t & 63;
    const float* Wt = sel ? WKt : WQt;
    __half* dh = (sel ? g_Kh : g_Qh) + (size_t)(v * 2 + b) * Nn * Hh;
    __half* dl = (sel ? g_Kl : g_Ql) + (size_t)(v * 2 + b) * Nn * Hh;
    float scale = sel ? 1.0f : 0.125f;
    int ebase = 84 + 32 * v;

    for (int nb = 0; nb < 128; nb += 8) {
        float acc[8] = {0, 0, 0, 0, 0, 0, 0, 0};
        for (int f = 0; f < 84; f++) {
            float w = Wt[f * 64 + j];
            #pragma unroll
            for (int u = 0; u < 8; u++)
                acc[u] = fmaf(Fs[f * 128 + nb + u], w, acc[u]);
        }
        #pragma unroll 8
        for (int e = 0; e < 32; e++) {
            float w = Wt[(84 + e) * 64 + j];
            #pragma unroll
            for (int u = 0; u < 8; u++)
                acc[u] = fmaf(Fs[(ebase + e) * 128 + nb + u], w, acc[u]);
        }
        #pragma unroll
        for (int u = 0; u < 8; u++) {
            float sv = acc[u] * scale;
            __half h = __float2half_rn(sv);
            float lo = sv - __half2float(h);
            size_t idx = (size_t)(node0 + nb + u) * Hh + j;
            dh[idx] = h;
            dl[idx] = __float2half_rn(lo);
        }
    }
}

// ---------------------------------------------------------------------------
// Kernel 3: scores = (0.125*Q) @ K^T via fp16 HMMA, 3-pass hi/lo (exact).
// ---------------------------------------------------------------------------
#define SCSTRIDE 72
#define SC_ARR (128 * SCSTRIDE * 2)
#define SC_SMEM (4 * SC_ARR)

__global__ void __launch_bounds__(256, 2) scores_mma_kernel(int c)
{
    extern __shared__ char dsm[];
    int row0 = blockIdx.y * 128, col0 = blockIdx.x * 128;
    int t = threadIdx.x, wid = t >> 5, lane = t & 31;
    int g = lane >> 2, tig = lane & 3;
    int wm = wid >> 2, wn = wid & 3;
    int lq = lane >> 3, lr = lane & 7;

    size_t qb = (size_t)c * Nn * Hh;
    uint32_t sb = s2u(dsm);
    uint32_t aQh = sb, aQl = sb + SC_ARR, aKh = sb + 2 * SC_ARR,
             aKl = sb + 3 * SC_ARR;

    #pragma unroll
    for (int j = 0; j < 16; j++) {
        int idx = j * 256 + t;
        int arr = idx >> 10;
        int rem = idx & 1023;
        int rr = rem >> 3, seg = rem & 7;
        const __half* base = (arr == 0) ? g_Qh : (arr == 1) ? g_Ql
                           : (arr == 2) ? g_Kh : g_Kl;
        int grow = ((arr < 2) ? row0 : col0) + rr;
        cpa16(sb + (uint32_t)arr * SC_ARR + rr * (SCSTRIDE * 2) + seg * 16,
              base + qb + (size_t)grow * Hh + seg * 8);
    }
    cpa_commit();
    cpa_wait<0>();
    __syncthreads();

    float acc[4][4][4] = {};
    #pragma unroll
    for (int ks = 0; ks < 4; ks++) {
        int kk = ks * 16;
        uint32_t qh[4][4], ql[4][4], kh[4][2], kl[4][2];
        #pragma unroll
        for (int ma = 0; ma < 4; ma++) {
            int row = wm * 64 + ma * 16 + (lq & 1) * 8 + lr;
            int col = kk + (lq >> 1) * 8;
            uint32_t off = (uint32_t)(row * SCSTRIDE + col) * 2;
            ldm4(qh[ma], aQh + off);
            ldm4(ql[ma], aQl + off);
        }
        #pragma unroll
        for (int np = 0; np < 2; np++) {
            int nrow = wn * 32 + np * 16 + (lq >> 1) * 8 + lr;
            int col = kk + (lq & 1) * 8;
            uint32_t off = (uint32_t)(nrow * SCSTRIDE + col) * 2;
            uint32_t r4[4];
            ldm4(r4, aKh + off);
            kh[np * 2][0] = r4[0]; kh[np * 2][1] = r4[1];
            kh[np * 2 + 1][0] = r4[2]; kh[np * 2 + 1][1] = r4[3];
            ldm4(r4, aKl + off);
            kl[np * 2][0] = r4[0]; kl[np * 2][1] = r4[1];
            kl[np * 2 + 1][0] = r4[2]; kl[np * 2 + 1][1] = r4[3];
        }
        #pragma unroll
        for (int ma = 0; ma < 4; ma++)
            #pragma unroll
            for (int na = 0; na < 4; na++) {
                mma16816h(acc[ma][na], qh[ma], kh[na]);
                mma16816h(acc[ma][na], qh[ma], kl[na]);
                mma16816h(acc[ma][na], ql[ma], kh[na]);
            }
    }

    float* S = g_S + (size_t)c * Nn * Nn;
    #pragma unroll
    for (int ma = 0; ma < 4; ma++)
        #pragma unroll
        for (int rr = 0; rr < 2; rr++) {
            int n = row0 + wm * 64 + ma * 16 + g + rr * 8;
            #pragma unroll
            for (int na = 0; na < 4; na++) {
                int col = col0 + wn * 32 + na * 8 + tig * 2;
                *(float2*)(S + (size_t)n * Nn + col) =
                    make_float2(acc[ma][na][rr * 2 + 0], acc[ma][na][rr * 2 + 1]);
            }
        }
}

// ---------------------------------------------------------------------------
// Kernel 4: fused masked softmax + normalize; emits order-1 output + fp16 A
// ---------------------------------------------------------------------------
__global__ void __launch_bounds__(256) softmax_kernel(
    const float* __restrict__ mask0, const float* __restrict__ mask1,
    float* __restrict__ out, int c)
{
    int n = blockIdx.x, v = c >> 1, b = c & 1;
    int t = threadIdx.x;
    const float* srow = g_S + ((size_t)c * Nn + n) * Nn;
    const float* mrow = (v ? mask1 : mask0) + (size_t)n * Nn;

    float s[8];
    float lmax = -3.4e38f;
    #pragma unroll
    for (int i = 0; i < 8; i++) {
        s[i] = srow[t + i * 256];
        lmax = fmaxf(lmax, s[i]);
    }

    __shared__ float red[8];
    #pragma unroll
    for (int o = 16; o; o >>= 1)
        lmax = fmaxf(lmax, __shfl_xor_sync(0xffffffffu, lmax, o));
    if ((t & 31) == 0) red[t >> 5] = lmax;
    __syncthreads();
    float rmax = red[0];
    #pragma unroll
    for (int w = 1; w < 8; w++) rmax = fmaxf(rmax, red[w]);
    __syncthreads();

    float wv[8], lsum = 0.0f;
    #pragma unroll
    for (int i = 0; i < 8; i++) {
        wv[i] = (mrow[t + i * 256] + 1e-7f) * expf(s[i] - rmax);
        lsum += wv[i];
    }
    #pragma unroll
    for (int o = 16; o; o >>= 1)
        lsum += __shfl_xor_sync(0xffffffffu, lsum, o);
    if ((t & 31) == 0) red[t >> 5] = lsum;
    __syncthreads();
    float tot = 0.0f;
    #pragma unroll
    for (int w = 0; w < 8; w++) tot += red[w];
    float inv = 1.0f / tot;

    size_t abase = ((size_t)c * Nn + n) * Nn;
    float* orow = out + (size_t)(v * 2) * OUT_G + (size_t)(b * Nn + n) * KTt * Nn;
    #pragma unroll
    for (int i = 0; i < 8; i++) {
        int m = t + i * 256;
        float val = wv[i] * inv;
        g_Ah[abase + m] = __float2half_rn(val);
        float ov = (m == n) ? 0.0f : val;
        orow[m] = ov;
        orow[Nn + m] = ov;
        orow[2 * Nn + m] = ov;
    }
}

// ---------------------------------------------------------------------------
// Kernel 5: C = A @ A via fp16 mma.sync, single pass, B via ldmatrix.trans.
// CTA 128x128, 4 warps of 64x64, K-chunk 64, double-buffered cp.async.
// ---------------------------------------------------------------------------
#define ASTRIDE 72
#define BSTRIDE 136
#define A_B (128 * ASTRIDE * 2)
#define B_B (64 * BSTRIDE * 2)
#define BUF_B (A_B + B_B)
#define SQ_SMEM (2 * BUF_B)

__global__ void __launch_bounds__(128, 2) sq_mma_kernel(float* __restrict__ out,
                                                        int c)
{
    extern __shared__ char dsm[];
    int v = c >> 1, b = c & 1;
    int row0 = blockIdx.y * 128, col0 = blockIdx.x * 128;
    int t = threadIdx.x, wid = t >> 5, lane = t & 31;
    int g = lane >> 2, tig = lane & 3;
    int wm = wid >> 1, wn = wid & 1;
    int lq = lane >> 3, lr = lane & 7;

    size_t cb = (size_t)c * Nn * Nn;
    const __half* Ahg = g_Ah + cb;

    uint32_t sbase = s2u(dsm);
    float acc[4][8][4] = {};

    auto load_stage = [&](int s, int kc) {
        uint32_t sb = sbase + (uint32_t)s * BUF_B;
        int k0 = kc * 64;
        #pragma unroll
        for (int j = 0; j < 8; j++) {
            int idx = j * 128 + t;
            int rr = idx >> 3, seg = idx & 7;
            cpa16(sb + rr * (ASTRIDE * 2) + seg * 16,
                  Ahg + (size_t)(row0 + rr) * Nn + k0 + seg * 8);
        }
        #pragma unroll
        for (int j = 0; j < 8; j++) {
            int idx = j * 128 + t;
            int rr = idx >> 4, seg = idx & 15;
            cpa16(sb + A_B + rr * (BSTRIDE * 2) + seg * 16,
                  Ahg + (size_t)(k0 + rr) * Nn + col0 + seg * 8);
        }
        cpa_commit();
    };

    load_stage(0, 0);

    int buf = 0;
    for (int kc = 0; kc < 32; kc++) {
        if (kc + 1 < 32) {
            load_stage(buf ^ 1, kc + 1);
            cpa_wait<1>();
        } else {
            cpa_wait<0>();
        }
        __syncthreads();

        uint32_t sb = sbase + (uint32_t)buf * BUF_B;
        uint32_t aA = sb, aB = sb + A_B;

        #pragma unroll
        for (int ks = 0; ks < 4; ks++) {
            int kk = ks * 16;
            uint32_t ah[4][4], bh[8][2];
            #pragma unroll
            for (int ma = 0; ma < 4; ma++) {
                int row = wm * 64 + ma * 16 + (lq & 1) * 8 + lr;
                int col = kk + (lq >> 1) * 8;
                ldm4(ah[ma], aA + (uint32_t)(row * ASTRIDE + col) * 2);
            }
            #pragma unroll
            for (int np = 0; np < 4; np++) {
                int row_k = kk + (lq & 1) * 8 + lr;
                int col_n = wn * 64 + np * 16 + (lq >> 1) * 8;
                uint32_t r4[4];
                ldm4t(r4, aB + (uint32_t)(row_k * BSTRIDE + col_n) * 2);
                bh[np * 2][0] = r4[0]; bh[np * 2][1] = r4[1];
                bh[np * 2 + 1][0] = r4[2]; bh[np * 2 + 1][1] = r4[3];
            }
            #pragma unroll
            for (int ma = 0; ma < 4; ma++)
                #pragma unroll
                for (int na = 0; na < 8; na++)
                    mma16816h(acc[ma][na], ah[ma], bh[na]);
        }
        __syncthreads();
        buf ^= 1;
    }

    float* obase = out + (size_t)(v * 2 + 1) * OUT_G;
    #pragma unroll
    for (int ma = 0; ma < 4; ma++) {
        #pragma unroll
        for (int rr = 0; rr < 2; rr++) {
            int n = row0 + wm * 64 + ma * 16 + g + rr * 8;
            size_t orow = (size_t)(b * Nn + n) * (KTt * Nn);
            #pragma unroll
            for (int na = 0; na < 8; na++) {
                int col = col0 + wn * 64 + na * 8 + tig * 2;
                float v0 = acc[ma][na][rr * 2 + 0];
                float v1 = acc[ma][na][rr * 2 + 1];
                if (n == col)     v0 = 0.0f;
                if (n == col + 1) v1 = 0.0f;
                float2 o = make_float2(v0, v1);
                *(float2*)(obase + orow + col)          = o;
                *(float2*)(obase + orow + Nn + col)     = o;
                *(float2*)(obase + orow + 2 * Nn + col) = o;
            }
        }
    }
}

// ---------------------------------------------------------------------------
extern "C" void kernel_launch(void* const* d_in, const int* in_sizes, int n_in,
                              void* d_out, int out_size)
{
    const float* hist = (const float*)d_in[0];
    const float* embd = (const float*)d_in[1];
    const float* embu = (const float*)d_in[2];
    const float* tdf  = (const float*)d_in[3];
    const float* dwf  = (const float*)d_in[4];
    const float* m0   = (const float*)d_in[5];
    const float* m1   = (const float*)d_in[6];
    const float* W1   = (const float*)d_in[7];
    const float* b1   = (const float*)d_in[8];
    const float* gam  = (const float*)d_in[9];
    const float* bet  = (const float*)d_in[10];
    const float* mu   = (const float*)d_in[11];
    const float* var  = (const float*)d_in[12];
    const float* W2   = (const float*)d_in[13];
    const float* b2   = (const float*)d_in[14];
    const float* WQ   = (const float*)d_in[15];
    const float* WK   = (const float*)d_in[16];
    float* out = (float*)d_out;

    // One-time host-side resources (created on the un-captured correctness
    // run). 3 side streams ONLY — the 4-branch fork shape tripped the
    // graph-upload mem guard in rounds 8/10; the 3+origin shape passed in
    // rounds 7/9/11.
    static cudaStream_t st[3] = {nullptr, nullptr, nullptr};
    static cudaEvent_t evf = nullptr, evj[3] = {nullptr, nullptr, nullptr};
    if (st[0] == nullptr) {
        int loPri = 0, hiPri = 0;
        cudaDeviceGetStreamPriorityRange(&loPri, &hiPri);  // hiPri = highest
        for (int i = 0; i < 3; i++) {
            int pri = hiPri + i;
            if (pri > loPri) pri = loPri;
            cudaStreamCreateWithPriority(&st[i], cudaStreamNonBlocking, pri);
            cudaEventCreateWithFlags(&evj[i], cudaEventDisableTiming);
        }
        cudaEventCreateWithFlags(&evf, cudaEventDisableTiming);
        cudaFuncSetAttribute(qk_kernel,
                             cudaFuncAttributeMaxDynamicSharedMemorySize, QK_SMEM);
        cudaFuncSetAttribute(scores_mma_kernel,
                             cudaFuncAttributeMaxDynamicSharedMemorySize, SC_SMEM);
        cudaFuncSetAttribute(sq_mma_kernel,
                             cudaFuncAttributeMaxDynamicSharedMemorySize, SQ_SMEM);
    }

    feat_kernel<<<dim3(Nn / 8, Bb), 128>>>(hist, embd, embu, tdf, dwf,
                                           W1, b1, gam, bet, mu, var, W2, b2);
    qk_kernel<<<dim3(Nn / 128, Bb), 256, QK_SMEM>>>(WQ, WK);

    // Fork: combo 0 on the capture-origin stream, combos 1..3 on st[0..2]
    // with descending priorities (soft stagger, no extra graph edges).
    cudaEventRecord(evf, 0);
    for (int i = 0; i < 3; i++) cudaStreamWaitEvent(st[i], evf, 0);

    scores_mma_kernel<<<dim3(16, 16, 1), 256, SC_SMEM>>>(0);
    for (int i = 0; i < 3; i++)
        scores_mma_kernel<<<dim3(16, 16, 1), 256, SC_SMEM, st[i]>>>(i + 1);

    softmax_kernel<<<dim3(Nn, 1), 256>>>(m0, m1, out, 0);
    for (int i = 0; i < 3; i++)
        softmax_kernel<<<dim3(Nn, 1), 256, 0, st[i]>>>(m0, m1, out, i + 1);

    sq_mma_kernel<<<dim3(16, 16, 1), 128, SQ_SMEM>>>(out, 0);
    for (int i = 0; i < 3; i++)
        sq_mma_kernel<<<dim3(16, 16, 1), 128, SQ_SMEM, st[i]>>>(out, i + 1);

    // Join
    for (int i = 0; i < 3; i++) {
        cudaEventRecord(evj[i], st[i]);
        cudaStreamWaitEvent(0, evj[i], 0);
    }
}